// round 1
// baseline (speedup 1.0000x reference)
#include <cuda_runtime.h>

// Problem constants
#define BQ   32
#define TT   512
#define DDIM 512
#define HH   8
#define HD   64
#define TEDIM 2048
#define MROWS (BQ*TT)            // 16384
#define YN ((size_t)BQ*TT*DDIM)  // 8388608
#define SN ((size_t)BQ*HH*TT*TT) // 67108864

// Scratch (device globals — no allocation allowed)
__device__ float g_xn[BQ*TT*DDIM];
__device__ float g_q [BQ*TT*DDIM];
__device__ float g_k [BQ*TT*DDIM];
__device__ float g_v [BQ*TT*DDIM];
__device__ float g_y [BQ*TT*DDIM];
__device__ float g_hs[BQ*TT*DDIM];
__device__ float g_sigma[BQ*HH*TT];
__device__ float g_style[BQ*2*DDIM];

__device__ __forceinline__ float siluf(float z){ return z / (1.f + expf(-z)); }

// ---------------------------------------------------------------------------
// LN1 + sigma:  xn = LN(x)*g+b ; sigma[b,h,t] = 3^(sigmoid(5*(x@Wsig))+1e-5)-1
// one block (256 thr) per row (b*T+t)
// ---------------------------------------------------------------------------
__global__ void ln1_sigma_kernel(const float* __restrict__ x,
                                 const float* __restrict__ g,
                                 const float* __restrict__ b,
                                 const float* __restrict__ Wsig)
{
    int row = blockIdx.x;
    int tid = threadIdx.x;
    int warp = tid >> 5, lane = tid & 31;
    const float* xr = x + (size_t)row * DDIM;
    float x0 = xr[tid], x1 = xr[tid + 256];
    float s = x0 + x1, sq = x0*x0 + x1*x1;
    #pragma unroll
    for (int o = 16; o > 0; o >>= 1) {
        s  += __shfl_xor_sync(~0u, s,  o);
        sq += __shfl_xor_sync(~0u, sq, o);
    }
    __shared__ float sm[8], sm2[8];
    if (lane == 0) { sm[warp] = s; sm2[warp] = sq; }
    __syncthreads();
    float tot = 0.f, tot2 = 0.f;
    #pragma unroll
    for (int i = 0; i < 8; i++) { tot += sm[i]; tot2 += sm2[i]; }
    float mean = tot * (1.f / DDIM);
    float var  = tot2 * (1.f / DDIM) - mean * mean;
    float rstd = rsqrtf(var + 1e-5f);
    g_xn[(size_t)row*DDIM + tid]       = (x0 - mean) * rstd * g[tid]       + b[tid];
    g_xn[(size_t)row*DDIM + tid + 256] = (x1 - mean) * rstd * g[tid + 256] + b[tid + 256];

    // sigma dots: acc[h] = sum_d x[d]*Wsig[d,h]
    float acc[HH];
    #pragma unroll
    for (int h = 0; h < HH; h++)
        acc[h] = x0 * Wsig[tid*HH + h] + x1 * Wsig[(tid+256)*HH + h];
    #pragma unroll
    for (int h = 0; h < HH; h++)
        #pragma unroll
        for (int o = 16; o > 0; o >>= 1)
            acc[h] += __shfl_xor_sync(~0u, acc[h], o);
    __shared__ float red[8][HH];
    if (lane == 0)
        #pragma unroll
        for (int h = 0; h < HH; h++) red[warp][h] = acc[h];
    __syncthreads();
    if (tid < HH) {
        float z = 0.f;
        #pragma unroll
        for (int w = 0; w < 8; w++) z += red[w][tid];
        float sg  = 1.f / (1.f + expf(-5.f * z)) + 1e-5f;
        float sig = exp2f(sg * 1.5849625007211562f) - 1.f;   // 3^sg - 1
        int bb = row / TT, t = row % TT;
        g_sigma[(bb*HH + tid)*TT + t] = sig;
    }
}

// ---------------------------------------------------------------------------
// Generic batched tiled SGEMM.
//   BT=true : C = scale * A[M,K] @ B[N,K]^T (+bias)(+res)
//   BT=false: C = scale * A[M,K] @ B[K,N]   (+bias)(+res)
// Batch offset for X = (z/divX)*sX1 + (z%divX)*sX2   (handles head slicing)
// Tiles: 64x64x16, 256 threads, 4x4 per thread.
// ---------------------------------------------------------------------------
template<bool BT>
__global__ void __launch_bounds__(256)
gemm_kernel(const float* __restrict__ A, const float* __restrict__ Bm,
            float* __restrict__ C,
            int K, int lda, int ldb, int ldc,
            int divA, long sA1, long sA2,
            int divB, long sB1, long sB2,
            int divC, long sC1, long sC2,
            float scale, const float* __restrict__ bias,
            const float* __restrict__ res, int ldres)
{
    int z = blockIdx.z;
    A  += (long)(z / divA) * sA1 + (long)(z % divA) * sA2;
    Bm += (long)(z / divB) * sB1 + (long)(z % divB) * sB2;
    C  += (long)(z / divC) * sC1 + (long)(z % divC) * sC2;

    __shared__ float As[16][65];
    __shared__ float Bs[16][65];

    int tid = threadIdx.x;
    int tx = tid & 15, ty = tid >> 4;
    int m0 = blockIdx.y * 64, n0 = blockIdx.x * 64;

    float acc[4][4] = {};

    for (int k0 = 0; k0 < K; k0 += 16) {
        {   // load A tile (row-major [M,K]) -> As[k][m]
            int r = tid >> 2, kq = (tid & 3) * 4;
            float4 a4 = *(const float4*)(A + (long)(m0 + r) * lda + k0 + kq);
            As[kq+0][r] = a4.x; As[kq+1][r] = a4.y;
            As[kq+2][r] = a4.z; As[kq+3][r] = a4.w;
        }
        if (BT) { // B is [N,K] row-major -> Bs[k][n]
            int r = tid >> 2, kq = (tid & 3) * 4;
            float4 b4 = *(const float4*)(Bm + (long)(n0 + r) * ldb + k0 + kq);
            Bs[kq+0][r] = b4.x; Bs[kq+1][r] = b4.y;
            Bs[kq+2][r] = b4.z; Bs[kq+3][r] = b4.w;
        } else {  // B is [K,N] row-major -> Bs[k][n]
            int kk = tid >> 4, nq = (tid & 15) * 4;
            float4 b4 = *(const float4*)(Bm + (long)(k0 + kk) * ldb + n0 + nq);
            Bs[kk][nq+0] = b4.x; Bs[kk][nq+1] = b4.y;
            Bs[kk][nq+2] = b4.z; Bs[kk][nq+3] = b4.w;
        }
        __syncthreads();
        #pragma unroll
        for (int k = 0; k < 16; k++) {
            float a[4], bv[4];
            #pragma unroll
            for (int i = 0; i < 4; i++) a[i]  = As[k][ty*4 + i];
            #pragma unroll
            for (int j = 0; j < 4; j++) bv[j] = Bs[k][tx*4 + j];
            #pragma unroll
            for (int i = 0; i < 4; i++)
                #pragma unroll
                for (int j = 0; j < 4; j++)
                    acc[i][j] += a[i] * bv[j];
        }
        __syncthreads();
    }

    #pragma unroll
    for (int i = 0; i < 4; i++) {
        int r = m0 + ty*4 + i;
        #pragma unroll
        for (int j = 0; j < 4; j++) {
            int c = n0 + tx*4 + j;
            float v = acc[i][j] * scale;
            if (bias) v += bias[c];
            if (res)  v += res[(long)r * ldres + c];
            C[(long)r * ldc + c] = v;
        }
    }
}

// ---------------------------------------------------------------------------
// softmax in-place over rows of 512; one warp per row, 8 rows per block
// ---------------------------------------------------------------------------
__global__ void softmax_kernel(float* __restrict__ S)
{
    int warp = threadIdx.x >> 5, lane = threadIdx.x & 31;
    long row = (long)blockIdx.x * 8 + warp;
    float* p = S + row * TT;
    float v[16];
    float mx = -1e30f;
    #pragma unroll
    for (int i = 0; i < 16; i++) { v[i] = p[lane + 32*i]; mx = fmaxf(mx, v[i]); }
    #pragma unroll
    for (int o = 16; o > 0; o >>= 1) mx = fmaxf(mx, __shfl_xor_sync(~0u, mx, o));
    float s = 0.f;
    #pragma unroll
    for (int i = 0; i < 16; i++) { v[i] = expf(v[i] - mx); s += v[i]; }
    #pragma unroll
    for (int o = 16; o > 0; o >>= 1) s += __shfl_xor_sync(~0u, s, o);
    float inv = 1.f / s;
    #pragma unroll
    for (int i = 0; i < 16; i++) p[lane + 32*i] = v[i] * inv;
}

// ---------------------------------------------------------------------------
// prior[b,h,n,m] = exp(-(n-m)^2/(2 s^2)) / (sqrt(2pi) s), sigma_full = s
// one block (128 thr) per (b,h,n) row; float4 stores
// ---------------------------------------------------------------------------
__global__ void prior_kernel(float* __restrict__ prior, float* __restrict__ sfull)
{
    long row = blockIdx.x;                 // (b*H+h)*T + n
    int n = (int)(row % TT);
    float s = g_sigma[row];
    float inv2 = -1.f / (2.f * s * s);
    float coef = 0.3989422804014327f / s;
    int tid = threadIdx.x;
    int m0 = tid * 4;
    float d0 = (float)(n - (m0 + 0));
    float d1 = (float)(n - (m0 + 1));
    float d2 = (float)(n - (m0 + 2));
    float d3 = (float)(n - (m0 + 3));
    float4 pv;
    pv.x = expf(d0*d0*inv2) * coef;
    pv.y = expf(d1*d1*inv2) * coef;
    pv.z = expf(d2*d2*inv2) * coef;
    pv.w = expf(d3*d3*inv2) * coef;
    ((float4*)(prior + row * TT))[tid] = pv;
    ((float4*)(sfull + row * TT))[tid] = make_float4(s, s, s, s);
}

// ---------------------------------------------------------------------------
// stylization: g_style[b, 0:1024] = silu(emb[b]) @ emb_W + emb_b
// grid (4, B), 256 threads; emb row cached (silu'd) in smem
// ---------------------------------------------------------------------------
__global__ void style_kernel(const float* __restrict__ emb,
                             const float* __restrict__ embW,
                             const float* __restrict__ embB)
{
    int bb = blockIdx.y, tid = threadIdx.x;
    __shared__ float se[TEDIM];
    for (int i = tid; i < TEDIM; i += 256) {
        float e = emb[(size_t)bb * TEDIM + i];
        se[i] = siluf(e);
    }
    __syncthreads();
    int j = blockIdx.x * 256 + tid;       // 0..1023
    float acc = 0.f;
    for (int k = 0; k < TEDIM; k++)
        acc += se[k] * embW[(size_t)k * (2*DDIM) + j];
    g_style[bb * (2*DDIM) + j] = acc + embB[j];
}

// ---------------------------------------------------------------------------
// LN2 + scale/shift + silu:  g_hs = silu( LN(g_y)*g+b * (1+scale) + shift )
// ---------------------------------------------------------------------------
__global__ void ln2_style_kernel(const float* __restrict__ g,
                                 const float* __restrict__ b)
{
    int row = blockIdx.x;
    int tid = threadIdx.x;
    int warp = tid >> 5, lane = tid & 31;
    int bb = row / TT;
    const float* yr = g_y + (size_t)row * DDIM;
    float x0 = yr[tid], x1 = yr[tid + 256];
    float s = x0 + x1, sq = x0*x0 + x1*x1;
    #pragma unroll
    for (int o = 16; o > 0; o >>= 1) {
        s  += __shfl_xor_sync(~0u, s,  o);
        sq += __shfl_xor_sync(~0u, sq, o);
    }
    __shared__ float sm[8], sm2[8];
    if (lane == 0) { sm[warp] = s; sm2[warp] = sq; }
    __syncthreads();
    float tot = 0.f, tot2 = 0.f;
    #pragma unroll
    for (int i = 0; i < 8; i++) { tot += sm[i]; tot2 += sm2[i]; }
    float mean = tot * (1.f / DDIM);
    float var  = tot2 * (1.f / DDIM) - mean * mean;
    float rstd = rsqrtf(var + 1e-5f);
    float n0 = (x0 - mean) * rstd * g[tid]       + b[tid];
    float n1 = (x1 - mean) * rstd * g[tid + 256] + b[tid + 256];
    const float* st = g_style + bb * (2*DDIM);
    float h0 = n0 * (1.f + st[tid])       + st[512 + tid];
    float h1 = n1 * (1.f + st[tid + 256]) + st[512 + tid + 256];
    g_hs[(size_t)row*DDIM + tid]       = siluf(h0);
    g_hs[(size_t)row*DDIM + tid + 256] = siluf(h1);
}

// ---------------------------------------------------------------------------
extern "C" void kernel_launch(void* const* d_in, const int* in_sizes, int n_in,
                              void* d_out, int out_size)
{
    const float* x    = (const float*)d_in[0];
    const float* emb  = (const float*)d_in[1];
    const float* Wq   = (const float*)d_in[2];
    const float* Wk   = (const float*)d_in[3];
    const float* Wv   = (const float*)d_in[4];
    const float* Wsig = (const float*)d_in[5];
    const float* ln1g = (const float*)d_in[6];
    const float* ln1b = (const float*)d_in[7];
    const float* embW = (const float*)d_in[8];
    const float* embB = (const float*)d_in[9];
    const float* ln2g = (const float*)d_in[10];
    const float* ln2b = (const float*)d_in[11];
    const float* outW = (const float*)d_in[12];
    const float* outB = (const float*)d_in[13];

    float* out    = (float*)d_out;
    float* outY   = out;
    float* outS   = out + YN;
    float* outP   = outS + SN;
    float* outSig = outP + SN;

    float *pxn, *pq, *pk, *pv, *py, *phs;
    cudaGetSymbolAddress((void**)&pxn, g_xn);
    cudaGetSymbolAddress((void**)&pq,  g_q);
    cudaGetSymbolAddress((void**)&pk,  g_k);
    cudaGetSymbolAddress((void**)&pv,  g_v);
    cudaGetSymbolAddress((void**)&py,  g_y);
    cudaGetSymbolAddress((void**)&phs, g_hs);

    // 1) LN1 + sigma
    ln1_sigma_kernel<<<MROWS, 256>>>(x, ln1g, ln1b, Wsig);

    // 2) Q/K/V = xn @ W^T   (M=16384, N=512, K=512)
    dim3 gq(DDIM/64, MROWS/64, 1);
    gemm_kernel<true><<<gq, 256>>>(pxn, Wq, pq, DDIM, DDIM, DDIM, DDIM,
        1,0,0, 1,0,0, 1,0,0, 1.f, nullptr, nullptr, 0);
    gemm_kernel<true><<<gq, 256>>>(pxn, Wk, pk, DDIM, DDIM, DDIM, DDIM,
        1,0,0, 1,0,0, 1,0,0, 1.f, nullptr, nullptr, 0);
    gemm_kernel<true><<<gq, 256>>>(pxn, Wv, pv, DDIM, DDIM, DDIM, DDIM,
        1,0,0, 1,0,0, 1,0,0, 1.f, nullptr, nullptr, 0);

    // 3) scores = Q @ K^T / 64  per (b,h)  -> series region
    dim3 gs(TT/64, TT/64, BQ*HH);
    gemm_kernel<true><<<gs, 256>>>(pq, pk, outS, HD, DDIM, DDIM, TT,
        HH, (long)TT*DDIM, (long)HD,
        HH, (long)TT*DDIM, (long)HD,
        1,  (long)TT*TT,   0,
        1.f/64.f, nullptr, nullptr, 0);

    // 4) softmax in place
    softmax_kernel<<<(unsigned)(SN/TT/8), 256>>>(outS);

    // 5) y = series @ V  per (b,h)  (M=512, N=64, K=512)
    dim3 ga(HD/64, TT/64, BQ*HH);
    gemm_kernel<false><<<ga, 256>>>(outS, pv, py, TT, TT, DDIM, DDIM,
        1,  (long)TT*TT,   0,
        HH, (long)TT*DDIM, (long)HD,
        HH, (long)TT*DDIM, (long)HD,
        1.f, nullptr, nullptr, 0);

    // 6) prior + sigma_full
    prior_kernel<<<BQ*HH*TT, 128>>>(outP, outSig);

    // 7) stylization embedding
    style_kernel<<<dim3(4, BQ), 256>>>(emb, embW, embB);

    // 8) LN2 + style + silu
    ln2_style_kernel<<<MROWS, 256>>>(ln2g, ln2b);

    // 9) y_out = x + silu_h @ out_W^T + out_b
    gemm_kernel<true><<<gq, 256>>>(phs, outW, outY, DDIM, DDIM, DDIM, DDIM,
        1,0,0, 1,0,0, 1,0,0, 1.f, outB, x, DDIM);
}

// round 2
// speedup vs baseline: 2.1783x; 2.1783x over previous
#include <cuda_runtime.h>

// Problem constants
#define BQ   32
#define TT   512
#define DDIM 512
#define HH   8
#define HD   64
#define TEDIM 2048
#define MROWS (BQ*TT)            // 16384
#define YN ((size_t)BQ*TT*DDIM)  // 8388608
#define SN ((size_t)BQ*HH*TT*TT) // 67108864

// Scratch (device globals — no allocation allowed)
__device__ float g_xn[BQ*TT*DDIM];
__device__ float g_q [BQ*TT*DDIM];
__device__ float g_k [BQ*TT*DDIM];
__device__ float g_v [BQ*TT*DDIM];   // stored TRANSPOSED: [b][h][d][t]
__device__ float g_y [BQ*TT*DDIM];
__device__ float g_hs[BQ*TT*DDIM];
__device__ float g_sigma[BQ*HH*TT];
__device__ float g_style[BQ*2*DDIM];

__device__ __forceinline__ float siluf(float z){ return z / (1.f + expf(-z)); }

__device__ __forceinline__ unsigned f2tf(float f){
    unsigned u; asm("cvt.rna.tf32.f32 %0, %1;" : "=r"(u) : "f"(f)); return u;
}

__device__ __forceinline__ void mma8(float* c,
    unsigned a0, unsigned a1, unsigned a2, unsigned a3,
    unsigned b0, unsigned b1)
{
    asm volatile(
        "mma.sync.aligned.m16n8k8.row.col.f32.tf32.tf32.f32 "
        "{%0,%1,%2,%3}, {%4,%5,%6,%7}, {%8,%9}, {%0,%1,%2,%3};"
        : "+f"(c[0]), "+f"(c[1]), "+f"(c[2]), "+f"(c[3])
        : "r"(a0), "r"(a1), "r"(a2), "r"(a3), "r"(b0), "r"(b1));
}

// ---------------------------------------------------------------------------
// LN1 + sigma:  xn = LN(x)*g+b ; sigma[b,h,t] = 3^(sigmoid(5*(x@Wsig))+1e-5)-1
// ---------------------------------------------------------------------------
__global__ void ln1_sigma_kernel(const float* __restrict__ x,
                                 const float* __restrict__ g,
                                 const float* __restrict__ b,
                                 const float* __restrict__ Wsig)
{
    int row = blockIdx.x;
    int tid = threadIdx.x;
    int warp = tid >> 5, lane = tid & 31;
    const float* xr = x + (size_t)row * DDIM;
    float x0 = xr[tid], x1 = xr[tid + 256];
    float s = x0 + x1, sq = x0*x0 + x1*x1;
    #pragma unroll
    for (int o = 16; o > 0; o >>= 1) {
        s  += __shfl_xor_sync(~0u, s,  o);
        sq += __shfl_xor_sync(~0u, sq, o);
    }
    __shared__ float sm[8], sm2[8];
    if (lane == 0) { sm[warp] = s; sm2[warp] = sq; }
    __syncthreads();
    float tot = 0.f, tot2 = 0.f;
    #pragma unroll
    for (int i = 0; i < 8; i++) { tot += sm[i]; tot2 += sm2[i]; }
    float mean = tot * (1.f / DDIM);
    float var  = tot2 * (1.f / DDIM) - mean * mean;
    float rstd = rsqrtf(var + 1e-5f);
    g_xn[(size_t)row*DDIM + tid]       = (x0 - mean) * rstd * g[tid]       + b[tid];
    g_xn[(size_t)row*DDIM + tid + 256] = (x1 - mean) * rstd * g[tid + 256] + b[tid + 256];

    float acc[HH];
    #pragma unroll
    for (int h = 0; h < HH; h++)
        acc[h] = x0 * Wsig[tid*HH + h] + x1 * Wsig[(tid+256)*HH + h];
    #pragma unroll
    for (int h = 0; h < HH; h++)
        #pragma unroll
        for (int o = 16; o > 0; o >>= 1)
            acc[h] += __shfl_xor_sync(~0u, acc[h], o);
    __shared__ float red[8][HH];
    if (lane == 0)
        #pragma unroll
        for (int h = 0; h < HH; h++) red[warp][h] = acc[h];
    __syncthreads();
    if (tid < HH) {
        float z = 0.f;
        #pragma unroll
        for (int w = 0; w < 8; w++) z += red[w][tid];
        float sg  = 1.f / (1.f + expf(-5.f * z)) + 1e-5f;
        float sig = exp2f(sg * 1.5849625007211562f) - 1.f;   // 3^sg - 1
        int bb = row / TT, t = row % TT;
        g_sigma[(bb*HH + tid)*TT + t] = sig;
    }
}

// ---------------------------------------------------------------------------
// tf32 tensor-core NT GEMM: C = scale * A[M,K] @ B[N,K]^T (+bias)(+res)
// BM=128, BN in {128,64}, BK=16. 256 threads, 8 warps (2m x 4n).
// Smem k-permuted layout: col = (k&3)*4 + (k>>2), row stride 20 ->
//   each thread's fragments for both k-steps come from single LDS.128s.
// TRANSC: scatter-store C for the V projection into [b,h,d,t] layout.
// ---------------------------------------------------------------------------
template<int BN, bool TRANSC>
__global__ void __launch_bounds__(256)
tf32_gemm(const float* __restrict__ A, const float* __restrict__ Bm,
          float* __restrict__ C, int K, int lda, int ldb, int ldc,
          int divA, long sA1, long sA2,
          int divB, long sB1, long sB2,
          int divC, long sC1, long sC2,
          float scale, const float* __restrict__ bias,
          const float* __restrict__ res, int ldres)
{
    constexpr int BM   = 128;
    constexpr int WT_N = BN / 4;   // per-warp n extent
    constexpr int NT   = WT_N / 8; // n8 tiles per warp
    constexpr int ST   = 20;       // smem row stride (floats)

    __shared__ unsigned As[2][BM*ST];
    __shared__ unsigned Bs[2][BN*ST];

    const int tid  = threadIdx.x;
    const int lane = tid & 31;
    const int g    = lane >> 2;    // 0..7
    const int t    = lane & 3;     // 0..3
    const int wid  = tid >> 5;
    const int wm   = wid & 1;      // 2 warps in m
    const int wn   = wid >> 1;     // 4 warps in n

    const int z = blockIdx.z;
    A  += (long)(z / divA) * sA1 + (long)(z % divA) * sA2;
    Bm += (long)(z / divB) * sB1 + (long)(z % divB) * sB2;
    if (!TRANSC)
        C += (long)(z / divC) * sC1 + (long)(z % divC) * sC2;

    const int m0 = blockIdx.y * BM;
    const int n0 = blockIdx.x * BN;

    const int rl = tid >> 2;       // 0..63  (tile row for global loads)
    const int q  = tid & 3;        // k-quad

    const float* Ag0 = A  + (long)(m0 + rl)      * lda + q*4;
    const float* Ag1 = A  + (long)(m0 + rl + 64) * lda + q*4;
    const float* Bg0 = Bm + (long)(n0 + rl)      * ldb + q*4;
    const float* Bg1 = Bm + (long)(n0 + ((BN==128)?(rl+64):rl)) * ldb + q*4;

    float4 pa0, pa1, pb0, pb1;

    auto gload = [&](int k0){
        pa0 = *(const float4*)(Ag0 + k0);
        pa1 = *(const float4*)(Ag1 + k0);
        pb0 = *(const float4*)(Bg0 + k0);
        if (BN == 128) pb1 = *(const float4*)(Bg1 + k0);
    };
    auto sstore = [&](int buf){
        const float* a0 = (const float*)&pa0;
        const float* a1 = (const float*)&pa1;
        const float* b0 = (const float*)&pb0;
        const float* b1 = (const float*)&pb1;
        #pragma unroll
        for (int j = 0; j < 4; j++){
            int c = j*4 + q;                 // permuted col for k = q*4+j
            As[buf][rl*ST + c]      = f2tf(a0[j]);
            As[buf][(rl+64)*ST + c] = f2tf(a1[j]);
            Bs[buf][rl*ST + c]      = f2tf(b0[j]);
            if (BN == 128) Bs[buf][(rl+64)*ST + c] = f2tf(b1[j]);
        }
    };

    float acc[4][NT][4];
    #pragma unroll
    for (int i = 0; i < 4; i++)
        #pragma unroll
        for (int j = 0; j < NT; j++)
            #pragma unroll
            for (int p = 0; p < 4; p++) acc[i][j][p] = 0.f;

    gload(0); sstore(0); __syncthreads();
    int buf = 0;
    for (int k0 = 16; k0 <= K; k0 += 16) {
        bool more = (k0 < K);
        if (more) gload(k0);

        uint4 alo[4], ahi[4];
        #pragma unroll
        for (int mt = 0; mt < 4; mt++){
            int r = wm*64 + mt*16 + g;
            alo[mt] = *(const uint4*)&As[buf][r*ST + 4*t];
            ahi[mt] = *(const uint4*)&As[buf][(r+8)*ST + 4*t];
        }
        #pragma unroll
        for (int nt = 0; nt < NT; nt++){
            uint4 bv = *(const uint4*)&Bs[buf][(wn*WT_N + nt*8 + g)*ST + 4*t];
            #pragma unroll
            for (int mt = 0; mt < 4; mt++){
                // k-step 0: a = {lo.x(hi? no: a0=lo.x, a1=hi.x, a2=lo.y, a3=hi.y}
                mma8(acc[mt][nt], alo[mt].x, ahi[mt].x, alo[mt].y, ahi[mt].y, bv.x, bv.y);
                // k-step 1
                mma8(acc[mt][nt], alo[mt].z, ahi[mt].z, alo[mt].w, ahi[mt].w, bv.z, bv.w);
            }
        }
        if (more){ sstore(buf^1); __syncthreads(); buf ^= 1; }
    }

    // Epilogue
    #pragma unroll
    for (int mt = 0; mt < 4; mt++){
        #pragma unroll
        for (int nt = 0; nt < NT; nt++){
            int row = m0 + wm*64 + mt*16 + g;
            int col = n0 + wn*WT_N + nt*8 + 2*t;
            float v0 = acc[mt][nt][0]*scale, v1 = acc[mt][nt][1]*scale;
            float v2 = acc[mt][nt][2]*scale, v3 = acc[mt][nt][3]*scale;
            if (bias){
                v0 += bias[col]; v1 += bias[col+1];
                v2 += bias[col]; v3 += bias[col+1];
            }
            if (res){
                v0 += res[(long)row*ldres + col];
                v1 += res[(long)row*ldres + col+1];
                v2 += res[(long)(row+8)*ldres + col];
                v3 += res[(long)(row+8)*ldres + col+1];
            }
            if (TRANSC){
                // V: row=(b*512+t_tok), col=(h*64+d) -> Vt[b][h][d][t_tok]
                long base0 = (long)(row >> 9) * (512L*512) + (row & 511);
                C[base0 + (long)col*512]     = v0;
                C[base0 + (long)(col+1)*512] = v1;
                C[base0 + 8 + (long)col*512]     = v2;   // row+8 same b
                C[base0 + 8 + (long)(col+1)*512] = v3;
            } else {
                *(float2*)&C[(long)row*ldc + col]     = make_float2(v0, v1);
                *(float2*)&C[(long)(row+8)*ldc + col] = make_float2(v2, v3);
            }
        }
    }
}

// ---------------------------------------------------------------------------
// softmax in-place over rows of 512; one warp per row, 8 rows per block
// ---------------------------------------------------------------------------
__global__ void softmax_kernel(float* __restrict__ S)
{
    int warp = threadIdx.x >> 5, lane = threadIdx.x & 31;
    long row = (long)blockIdx.x * 8 + warp;
    float* p = S + row * TT;
    float v[16];
    float mx = -1e30f;
    #pragma unroll
    for (int i = 0; i < 16; i++) { v[i] = p[lane + 32*i]; mx = fmaxf(mx, v[i]); }
    #pragma unroll
    for (int o = 16; o > 0; o >>= 1) mx = fmaxf(mx, __shfl_xor_sync(~0u, mx, o));
    float s = 0.f;
    #pragma unroll
    for (int i = 0; i < 16; i++) { v[i] = __expf(v[i] - mx); s += v[i]; }
    #pragma unroll
    for (int o = 16; o > 0; o >>= 1) s += __shfl_xor_sync(~0u, s, o);
    float inv = 1.f / s;
    #pragma unroll
    for (int i = 0; i < 16; i++) p[lane + 32*i] = v[i] * inv;
}

// ---------------------------------------------------------------------------
// prior + sigma_full
// ---------------------------------------------------------------------------
__global__ void prior_kernel(float* __restrict__ prior, float* __restrict__ sfull)
{
    long row = blockIdx.x;                 // (b*H+h)*T + n
    int n = (int)(row % TT);
    float s = g_sigma[row];
    float inv2 = -1.f / (2.f * s * s);
    float coef = 0.3989422804014327f / s;
    int tid = threadIdx.x;
    int m0 = tid * 4;
    float d0 = (float)(n - (m0 + 0));
    float d1 = (float)(n - (m0 + 1));
    float d2 = (float)(n - (m0 + 2));
    float d3 = (float)(n - (m0 + 3));
    float4 pv;
    pv.x = __expf(d0*d0*inv2) * coef;
    pv.y = __expf(d1*d1*inv2) * coef;
    pv.z = __expf(d2*d2*inv2) * coef;
    pv.w = __expf(d3*d3*inv2) * coef;
    ((float4*)(prior + row * TT))[tid] = pv;
    ((float4*)(sfull + row * TT))[tid] = make_float4(s, s, s, s);
}

// ---------------------------------------------------------------------------
// stylization: g_style[b, 0:1024] = silu(emb[b]) @ emb_W + emb_b
// ---------------------------------------------------------------------------
__global__ void style_kernel(const float* __restrict__ emb,
                             const float* __restrict__ embW,
                             const float* __restrict__ embB)
{
    int bb = blockIdx.y, tid = threadIdx.x;
    __shared__ float se[TEDIM];
    for (int i = tid; i < TEDIM; i += 256) {
        float e = emb[(size_t)bb * TEDIM + i];
        se[i] = siluf(e);
    }
    __syncthreads();
    int j = blockIdx.x * 256 + tid;       // 0..1023
    float acc = 0.f;
    for (int k = 0; k < TEDIM; k++)
        acc += se[k] * embW[(size_t)k * (2*DDIM) + j];
    g_style[bb * (2*DDIM) + j] = acc + embB[j];
}

// ---------------------------------------------------------------------------
// LN2 + scale/shift + silu
// ---------------------------------------------------------------------------
__global__ void ln2_style_kernel(const float* __restrict__ g,
                                 const float* __restrict__ b)
{
    int row = blockIdx.x;
    int tid = threadIdx.x;
    int warp = tid >> 5, lane = tid & 31;
    int bb = row / TT;
    const float* yr = g_y + (size_t)row * DDIM;
    float x0 = yr[tid], x1 = yr[tid + 256];
    float s = x0 + x1, sq = x0*x0 + x1*x1;
    #pragma unroll
    for (int o = 16; o > 0; o >>= 1) {
        s  += __shfl_xor_sync(~0u, s,  o);
        sq += __shfl_xor_sync(~0u, sq, o);
    }
    __shared__ float sm[8], sm2[8];
    if (lane == 0) { sm[warp] = s; sm2[warp] = sq; }
    __syncthreads();
    float tot = 0.f, tot2 = 0.f;
    #pragma unroll
    for (int i = 0; i < 8; i++) { tot += sm[i]; tot2 += sm2[i]; }
    float mean = tot * (1.f / DDIM);
    float var  = tot2 * (1.f / DDIM) - mean * mean;
    float rstd = rsqrtf(var + 1e-5f);
    float n0 = (x0 - mean) * rstd * g[tid]       + b[tid];
    float n1 = (x1 - mean) * rstd * g[tid + 256] + b[tid + 256];
    const float* st = g_style + bb * (2*DDIM);
    float h0 = n0 * (1.f + st[tid])       + st[512 + tid];
    float h1 = n1 * (1.f + st[tid + 256]) + st[512 + tid + 256];
    g_hs[(size_t)row*DDIM + tid]       = siluf(h0);
    g_hs[(size_t)row*DDIM + tid + 256] = siluf(h1);
}

// ---------------------------------------------------------------------------
extern "C" void kernel_launch(void* const* d_in, const int* in_sizes, int n_in,
                              void* d_out, int out_size)
{
    const float* x    = (const float*)d_in[0];
    const float* emb  = (const float*)d_in[1];
    const float* Wq   = (const float*)d_in[2];
    const float* Wk   = (const float*)d_in[3];
    const float* Wv   = (const float*)d_in[4];
    const float* Wsig = (const float*)d_in[5];
    const float* ln1g = (const float*)d_in[6];
    const float* ln1b = (const float*)d_in[7];
    const float* embW = (const float*)d_in[8];
    const float* embB = (const float*)d_in[9];
    const float* ln2g = (const float*)d_in[10];
    const float* ln2b = (const float*)d_in[11];
    const float* outW = (const float*)d_in[12];
    const float* outB = (const float*)d_in[13];

    float* out    = (float*)d_out;
    float* outY   = out;
    float* outS   = out + YN;
    float* outP   = outS + SN;
    float* outSig = outP + SN;

    float *pxn, *pq, *pk, *pv, *py, *phs;
    cudaGetSymbolAddress((void**)&pxn, g_xn);
    cudaGetSymbolAddress((void**)&pq,  g_q);
    cudaGetSymbolAddress((void**)&pk,  g_k);
    cudaGetSymbolAddress((void**)&pv,  g_v);
    cudaGetSymbolAddress((void**)&py,  g_y);
    cudaGetSymbolAddress((void**)&phs, g_hs);

    // 1) LN1 + sigma
    ln1_sigma_kernel<<<MROWS, 256>>>(x, ln1g, ln1b, Wsig);

    // 2) Q/K = xn @ W^T  (M=16384, N=512, K=512); V same but transposed store
    dim3 gq(DDIM/128, MROWS/128, 1);
    tf32_gemm<128,false><<<gq, 256>>>(pxn, Wq, pq, DDIM, DDIM, DDIM, DDIM,
        1,0,0, 1,0,0, 1,0,0, 1.f, nullptr, nullptr, 0);
    tf32_gemm<128,false><<<gq, 256>>>(pxn, Wk, pk, DDIM, DDIM, DDIM, DDIM,
        1,0,0, 1,0,0, 1,0,0, 1.f, nullptr, nullptr, 0);
    tf32_gemm<128,true><<<gq, 256>>>(pxn, Wv, pv, DDIM, DDIM, DDIM, DDIM,
        1,0,0, 1,0,0, 1,0,0, 1.f, nullptr, nullptr, 0);

    // 3) scores = Q @ K^T / 64  per (b,h)
    dim3 gs(TT/128, TT/128, BQ*HH);
    tf32_gemm<128,false><<<gs, 256>>>(pq, pk, outS, HD, DDIM, DDIM, TT,
        HH, (long)TT*DDIM, (long)HD,
        HH, (long)TT*DDIM, (long)HD,
        1,  (long)TT*TT,   0,
        1.f/64.f, nullptr, nullptr, 0);

    // 4) softmax in place
    softmax_kernel<<<(unsigned)(SN/TT/8), 256>>>(outS);

    // 5) y = series @ Vt^T  per (b,h): A=[512,512], B=Vt[bh] [64,512] -> NT
    dim3 ga(1, TT/128, BQ*HH);
    tf32_gemm<64,false><<<ga, 256>>>(outS, pv, py, TT, TT, DDIM, DDIM,
        1,  (long)TT*TT,    0,
        1,  (long)HD*DDIM,  0,
        HH, (long)TT*DDIM,  (long)HD,
        1.f, nullptr, nullptr, 0);

    // 6) prior + sigma_full
    prior_kernel<<<BQ*HH*TT, 128>>>(outP, outSig);

    // 7) stylization embedding
    style_kernel<<<dim3(4, BQ), 256>>>(emb, embW, embB);

    // 8) LN2 + style + silu
    ln2_style_kernel<<<MROWS, 256>>>(ln2g, ln2b);

    // 9) y_out = x + silu_h @ out_W^T + out_b
    tf32_gemm<128,false><<<gq, 256>>>(phs, outW, outY, DDIM, DDIM, DDIM, DDIM,
        1,0,0, 1,0,0, 1,0,0, 1.f, outB, x, DDIM);
}

// round 3
// speedup vs baseline: 2.9022x; 1.3323x over previous
#include <cuda_runtime.h>

// Problem constants
#define BQ   32
#define TT   512
#define DDIM 512
#define HH   8
#define HD   64
#define TEDIM 2048
#define MROWS (BQ*TT)            // 16384
#define YN ((size_t)BQ*TT*DDIM)  // 8388608
#define SN ((size_t)BQ*HH*TT*TT) // 67108864
#define WSZ (DDIM*DDIM)          // 262144

// Scratch (device globals — no allocation allowed)
__device__ float g_xn[BQ*TT*DDIM];
__device__ float g_q [BQ*TT*DDIM];
__device__ float g_k [BQ*TT*DDIM];
__device__ float g_v [BQ*TT*DDIM];   // stored TRANSPOSED: [b][h][d][t]
__device__ float g_y [BQ*TT*DDIM];
__device__ float g_hs[BQ*TT*DDIM];
__device__ float g_sigma[BQ*HH*TT];
__device__ float g_style[BQ*2*DDIM];
__device__ float g_wr[4*WSZ];        // tf32-rounded Wq,Wk,Wv,outW

__device__ __forceinline__ float siluf(float z){ return z / (1.f + expf(-z)); }

__device__ __forceinline__ float tf32r(float f){
    unsigned u; asm("cvt.rna.tf32.f32 %0, %1;" : "=r"(u) : "f"(f));
    return __uint_as_float(u);
}

__device__ __forceinline__ void mma8(float* c,
    unsigned a0, unsigned a1, unsigned a2, unsigned a3,
    unsigned b0, unsigned b1)
{
    asm volatile(
        "mma.sync.aligned.m16n8k8.row.col.f32.tf32.tf32.f32 "
        "{%0,%1,%2,%3}, {%4,%5,%6,%7}, {%8,%9}, {%0,%1,%2,%3};"
        : "+f"(c[0]), "+f"(c[1]), "+f"(c[2]), "+f"(c[3])
        : "r"(a0), "r"(a1), "r"(a2), "r"(a3), "r"(b0), "r"(b1));
}

__device__ __forceinline__ void cp16(unsigned dst, const void* src){
    asm volatile("cp.async.cg.shared.global [%0], [%1], 16;" :: "r"(dst), "l"(src));
}
#define CPCOMMIT() asm volatile("cp.async.commit_group;" ::: "memory")
#define CPWAIT(n)  asm volatile("cp.async.wait_group %0;" :: "n"(n) : "memory")

__device__ __forceinline__ uint4 ldmx4(unsigned a){
    uint4 r;
    asm volatile("ldmatrix.sync.aligned.m8n8.x4.shared.b16 {%0,%1,%2,%3}, [%4];"
        : "=r"(r.x), "=r"(r.y), "=r"(r.z), "=r"(r.w) : "r"(a));
    return r;
}

// ---------------------------------------------------------------------------
// weight pre-round: g_wr slabs = tf32(Wq),tf32(Wk),tf32(Wv),tf32(outW)
// ---------------------------------------------------------------------------
__global__ void round_w_kernel(const float* __restrict__ w0, const float* __restrict__ w1,
                               const float* __restrict__ w2, const float* __restrict__ w3)
{
    int i = blockIdx.x * 256 + threadIdx.x;
    g_wr[i]         = tf32r(w0[i]);
    g_wr[i +   WSZ] = tf32r(w1[i]);
    g_wr[i + 2*WSZ] = tf32r(w2[i]);
    g_wr[i + 3*WSZ] = tf32r(w3[i]);
}

// ---------------------------------------------------------------------------
// LN1 + sigma (xn stored tf32-rounded)
// ---------------------------------------------------------------------------
__global__ void ln1_sigma_kernel(const float* __restrict__ x,
                                 const float* __restrict__ g,
                                 const float* __restrict__ b,
                                 const float* __restrict__ Wsig)
{
    int row = blockIdx.x;
    int tid = threadIdx.x;
    int warp = tid >> 5, lane = tid & 31;
    const float* xr = x + (size_t)row * DDIM;
    float x0 = xr[tid], x1 = xr[tid + 256];
    float s = x0 + x1, sq = x0*x0 + x1*x1;
    #pragma unroll
    for (int o = 16; o > 0; o >>= 1) {
        s  += __shfl_xor_sync(~0u, s,  o);
        sq += __shfl_xor_sync(~0u, sq, o);
    }
    __shared__ float sm[8], sm2[8];
    if (lane == 0) { sm[warp] = s; sm2[warp] = sq; }
    __syncthreads();
    float tot = 0.f, tot2 = 0.f;
    #pragma unroll
    for (int i = 0; i < 8; i++) { tot += sm[i]; tot2 += sm2[i]; }
    float mean = tot * (1.f / DDIM);
    float var  = tot2 * (1.f / DDIM) - mean * mean;
    float rstd = rsqrtf(var + 1e-5f);
    g_xn[(size_t)row*DDIM + tid]       = tf32r((x0 - mean) * rstd * g[tid]       + b[tid]);
    g_xn[(size_t)row*DDIM + tid + 256] = tf32r((x1 - mean) * rstd * g[tid + 256] + b[tid + 256]);

    float acc[HH];
    #pragma unroll
    for (int h = 0; h < HH; h++)
        acc[h] = x0 * Wsig[tid*HH + h] + x1 * Wsig[(tid+256)*HH + h];
    #pragma unroll
    for (int h = 0; h < HH; h++)
        #pragma unroll
        for (int o = 16; o > 0; o >>= 1)
            acc[h] += __shfl_xor_sync(~0u, acc[h], o);
    __shared__ float red[8][HH];
    if (lane == 0)
        #pragma unroll
        for (int h = 0; h < HH; h++) red[warp][h] = acc[h];
    __syncthreads();
    if (tid < HH) {
        float z = 0.f;
        #pragma unroll
        for (int w = 0; w < 8; w++) z += red[w][tid];
        float sg  = 1.f / (1.f + expf(-5.f * z)) + 1e-5f;
        float sig = exp2f(sg * 1.5849625007211562f) - 1.f;   // 3^sg - 1
        int bb = row / TT, t = row % TT;
        g_sigma[(bb*HH + tid)*TT + t] = sig;
    }
}

// ---------------------------------------------------------------------------
// tf32 tensor-core NT GEMM: C = scale * A[M,K] @ B[N,K]^T (+bias)(+res)
// BM=128, BK=16, 3-stage cp.async pipeline, ldmatrix fragments.
// 256 threads = 8 warps (2m x 4n). Inputs must be tf32-pre-rounded.
// ---------------------------------------------------------------------------
template<int BN, bool TRANSC, bool ROUND>
__global__ void __launch_bounds__(256,2)
tf32_gemm(const float* __restrict__ A, const float* __restrict__ Bm,
          float* __restrict__ C, int K, int lda, int ldb, int ldc,
          int divA, long sA1, long sA2,
          int divB, long sB1, long sB2,
          int divC, long sC1, long sC2,
          float scale, const float* __restrict__ bias,
          const float* __restrict__ res, int ldres)
{
    constexpr int ST   = 20;                 // smem row stride (floats), 80B
    constexpr int ASTB = 128*ST*4;           // A stage bytes
    constexpr int BSTB = BN*ST*4;            // B stage bytes
    constexpr int WT_N = BN / 4;
    constexpr int NT   = WT_N / 8;

    extern __shared__ float dsm[];
    const unsigned sb = (unsigned)__cvta_generic_to_shared(dsm);
    const unsigned aS = sb;
    const unsigned bS = sb + 3*ASTB;

    const int tid  = threadIdx.x;
    const int lane = tid & 31;
    const int wid  = tid >> 5;
    const int wm   = wid & 1;
    const int wn   = wid >> 1;
    const int g    = lane >> 2;
    const int t    = lane & 3;

    const int z = blockIdx.z;
    A  += (long)(z / divA) * sA1 + (long)(z % divA) * sA2;
    Bm += (long)(z / divB) * sB1 + (long)(z % divB) * sB2;
    if (!TRANSC)
        C += (long)(z / divC) * sC1 + (long)(z % divC) * sC2;

    const int m0 = blockIdx.y * 128;
    const int n0 = blockIdx.x * BN;

    const int rl = tid >> 2;       // 0..63
    const int q  = tid & 3;        // 16B chunk within BK16

    const float* Ag0 = A  + (long)(m0 + rl) * lda + q*4;
    const float* Ag1 = Ag0 + 64L * lda;
    const float* Bg0 = Bm + (long)(n0 + rl) * ldb + q*4;
    const float* Bg1 = Bg0 + 64L * ldb;

    const unsigned d0 = (unsigned)(rl*ST + q*4) * 4;
    const unsigned d1 = (unsigned)((rl+64)*ST + q*4) * 4;

    // fragment base offsets (bytes)
    const int arow = (lane & 7) + ((lane >> 3) & 1) * 8;
    const int acol = (lane >> 4) * 4;
    const unsigned aFB = (unsigned)((wm*64 + arow)*ST + acol) * 4;
    const unsigned bFB = (unsigned)((wn*WT_N + (lane & 7))*ST + (lane >> 3)*4) * 4;

    float acc[4][NT][4];
    #pragma unroll
    for (int i = 0; i < 4; i++)
        #pragma unroll
        for (int j = 0; j < NT; j++)
            #pragma unroll
            for (int p = 0; p < 4; p++) acc[i][j][p] = 0.f;

    auto issue = [&](int st, int k0){
        unsigned ab = aS + st*ASTB, bb = bS + st*BSTB;
        cp16(ab + d0, Ag0 + k0);
        cp16(ab + d1, Ag1 + k0);
        cp16(bb + d0, Bg0 + k0);
        if (BN == 128) cp16(bb + d1, Bg1 + k0);
    };

    issue(0, 0);  CPCOMMIT();
    issue(1, 16); CPCOMMIT();

    int buf = 0;
    for (int k0 = 0; k0 < K; k0 += 16) {
        CPWAIT(1);
        __syncthreads();
        if (k0 + 32 < K) {
            int nb = buf + 2; if (nb >= 3) nb -= 3;
            issue(nb, k0 + 32);
        }
        CPCOMMIT();

        const unsigned ab = aS + buf*ASTB;
        const unsigned bb = bS + buf*BSTB;

        uint4 bfr[NT];
        #pragma unroll
        for (int nt = 0; nt < NT; nt++)
            bfr[nt] = ldmx4(bb + bFB + (unsigned)(nt*8*ST*4));

        #pragma unroll
        for (int ks = 0; ks < 2; ks++) {
            #pragma unroll
            for (int mt = 0; mt < 4; mt++) {
                uint4 a = ldmx4(ab + aFB + (unsigned)(mt*16*ST*4 + ks*32));
                #pragma unroll
                for (int nt = 0; nt < NT; nt++)
                    mma8(acc[mt][nt], a.x, a.y, a.z, a.w,
                         ks ? bfr[nt].z : bfr[nt].x,
                         ks ? bfr[nt].w : bfr[nt].y);
            }
        }
        buf++; if (buf == 3) buf = 0;
    }

    // Epilogue
    #pragma unroll
    for (int mt = 0; mt < 4; mt++){
        #pragma unroll
        for (int nt = 0; nt < NT; nt++){
            int row = m0 + wm*64 + mt*16 + g;
            int col = n0 + wn*WT_N + nt*8 + 2*t;
            float v0 = acc[mt][nt][0]*scale, v1 = acc[mt][nt][1]*scale;
            float v2 = acc[mt][nt][2]*scale, v3 = acc[mt][nt][3]*scale;
            if (bias){
                v0 += bias[col]; v1 += bias[col+1];
                v2 += bias[col]; v3 += bias[col+1];
            }
            if (res){
                v0 += res[(long)row*ldres + col];
                v1 += res[(long)row*ldres + col+1];
                v2 += res[(long)(row+8)*ldres + col];
                v3 += res[(long)(row+8)*ldres + col+1];
            }
            if (ROUND){
                v0 = tf32r(v0); v1 = tf32r(v1); v2 = tf32r(v2); v3 = tf32r(v3);
            }
            if (TRANSC){
                long base0 = (long)(row >> 9) * (512L*512) + (row & 511);
                C[base0 + (long)col*512]         = v0;
                C[base0 + (long)(col+1)*512]     = v1;
                C[base0 + 8 + (long)col*512]     = v2;
                C[base0 + 8 + (long)(col+1)*512] = v3;
            } else {
                *(float2*)&C[(long)row*ldc + col]     = make_float2(v0, v1);
                *(float2*)&C[(long)(row+8)*ldc + col] = make_float2(v2, v3);
            }
        }
    }
}

// ---------------------------------------------------------------------------
// Fused scores + softmax: series[bh, 32-row slab, :] directly.
// BM=32, full N=512 held in accumulators (64 f32/thread).
// K operand streamed in 4 chunks of 128 rows, cp.async double-buffered.
// warps: 2m x 4n; warp n-slice = 32 cols per 128-chunk.
// ---------------------------------------------------------------------------
__global__ void __launch_bounds__(256,2)
fused_scores_kernel(const float* __restrict__ Q, const float* __restrict__ Kt,
                    float* __restrict__ S)
{
    constexpr int AST = 68;   // A row stride floats (64 + 4)
    constexpr int BST = 68;
    const unsigned A_BYTES = 32*AST*4;            // 8704
    const unsigned B_BYTES = 128*BST*4;           // 34816

    extern __shared__ float dsm[];
    const unsigned sb  = (unsigned)__cvta_generic_to_shared(dsm);
    const unsigned sbA = sb;
    const unsigned sbB = sb + A_BYTES;
    float* red = dsm + (A_BYTES + 2*B_BYTES)/4;   // [32][4]

    const int tid  = threadIdx.x;
    const int lane = tid & 31;
    const int wid  = tid >> 5;
    const int wm   = wid & 1;
    const int wn   = wid >> 1;        // 0..3
    const int g    = lane >> 2;
    const int t    = lane & 3;

    const int bh = blockIdx.y;        // b*8+h
    const int b  = bh >> 3, h = bh & 7;
    const int m0 = blockIdx.x * 32;

    const float* Qb = Q + ((long)b*512 + m0)*512 + h*64;
    const float* Kb = Kt + ((long)b*512)*512 + h*64;
    float* Sb = S + ((long)bh*512 + m0)*512;

    // fragment addr helpers
    const int arow = (lane & 7) + ((lane >> 3) & 1) * 8;
    const int acol = (lane >> 4) * 4;
    const unsigned aF = sbA + (unsigned)((wm*16 + arow)*AST + acol) * 4;
    const unsigned bF = (unsigned)((wn*32 + (lane & 7))*BST + (lane >> 3)*4) * 4;

    auto issueB = [&](int chunk, int bufb){
        unsigned dst = sbB + (unsigned)bufb * B_BYTES;
        const float* src = Kb + (long)(chunk*128)*512;
        #pragma unroll
        for (int e = 0; e < 8; e++){
            int idx = tid + 256*e;
            int r = idx >> 4, c4 = idx & 15;
            cp16(dst + (unsigned)(r*BST + c4*4)*4, src + (long)r*512 + c4*4);
        }
    };

    // group 0: A + chunk0
    {
        #pragma unroll
        for (int e = 0; e < 2; e++){
            int idx = tid + 256*e;
            int r = idx >> 4, c4 = idx & 15;
            cp16(sbA + (unsigned)(r*AST + c4*4)*4, Qb + (long)r*512 + c4*4);
        }
        issueB(0, 0);
        CPCOMMIT();
    }

    float acc[4][4][4];
    #pragma unroll
    for (int c = 0; c < 4; c++)
        #pragma unroll
        for (int nt = 0; nt < 4; nt++)
            #pragma unroll
            for (int p = 0; p < 4; p++) acc[c][nt][p] = 0.f;

    for (int c = 0; c < 4; c++){
        CPWAIT(0);
        __syncthreads();
        if (c + 1 < 4) issueB(c + 1, (c + 1) & 1);
        CPCOMMIT();

        const unsigned bb = sbB + (unsigned)(c & 1) * B_BYTES;
        #pragma unroll
        for (int kg = 0; kg < 4; kg++){
            uint4 a0 = ldmx4(aF + (unsigned)(kg*16 + 0)*4);   // ks=2kg   (cols kg*16..)
            uint4 a1 = ldmx4(aF + (unsigned)(kg*16 + 8)*4);   // ks=2kg+1
            #pragma unroll
            for (int nt = 0; nt < 4; nt++){
                uint4 bv = ldmx4(bb + bF + (unsigned)(nt*8*BST + kg*16)*4);
                mma8(acc[c][nt], a0.x, a0.y, a0.z, a0.w, bv.x, bv.y);
                mma8(acc[c][nt], a1.x, a1.y, a1.z, a1.w, bv.z, bv.w);
            }
        }
        __syncthreads();  // all reads of this buf done before it's refilled
    }

    // scale by 1/64
    #pragma unroll
    for (int c = 0; c < 4; c++)
        #pragma unroll
        for (int nt = 0; nt < 4; nt++)
            #pragma unroll
            for (int p = 0; p < 4; p++) acc[c][nt][p] *= (1.f/64.f);

    const int r0 = wm*16 + g, r1 = r0 + 8;

    // row max (local -> quad -> cross-warp via smem)
    float mx0 = -1e30f, mx1 = -1e30f;
    #pragma unroll
    for (int c = 0; c < 4; c++)
        #pragma unroll
        for (int nt = 0; nt < 4; nt++){
            mx0 = fmaxf(mx0, fmaxf(acc[c][nt][0], acc[c][nt][1]));
            mx1 = fmaxf(mx1, fmaxf(acc[c][nt][2], acc[c][nt][3]));
        }
    #pragma unroll
    for (int o = 1; o <= 2; o <<= 1){
        mx0 = fmaxf(mx0, __shfl_xor_sync(~0u, mx0, o));
        mx1 = fmaxf(mx1, __shfl_xor_sync(~0u, mx1, o));
    }
    if (t == 0){ red[r0*4 + wn] = mx0; red[r1*4 + wn] = mx1; }
    __syncthreads();
    float rm0 = fmaxf(fmaxf(red[r0*4+0], red[r0*4+1]), fmaxf(red[r0*4+2], red[r0*4+3]));
    float rm1 = fmaxf(fmaxf(red[r1*4+0], red[r1*4+1]), fmaxf(red[r1*4+2], red[r1*4+3]));
    __syncthreads();

    // exp + row sum
    float s0 = 0.f, s1 = 0.f;
    #pragma unroll
    for (int c = 0; c < 4; c++)
        #pragma unroll
        for (int nt = 0; nt < 4; nt++){
            acc[c][nt][0] = __expf(acc[c][nt][0] - rm0);
            acc[c][nt][1] = __expf(acc[c][nt][1] - rm0);
            acc[c][nt][2] = __expf(acc[c][nt][2] - rm1);
            acc[c][nt][3] = __expf(acc[c][nt][3] - rm1);
            s0 += acc[c][nt][0] + acc[c][nt][1];
            s1 += acc[c][nt][2] + acc[c][nt][3];
        }
    #pragma unroll
    for (int o = 1; o <= 2; o <<= 1){
        s0 += __shfl_xor_sync(~0u, s0, o);
        s1 += __shfl_xor_sync(~0u, s1, o);
    }
    if (t == 0){ red[r0*4 + wn] = s0; red[r1*4 + wn] = s1; }
    __syncthreads();
    float inv0 = 1.f / (red[r0*4+0] + red[r0*4+1] + red[r0*4+2] + red[r0*4+3]);
    float inv1 = 1.f / (red[r1*4+0] + red[r1*4+1] + red[r1*4+2] + red[r1*4+3]);

    // store (tf32-rounded: series feeds the AV mma)
    float* p0 = Sb + (long)r0*512;
    float* p1 = Sb + (long)r1*512;
    #pragma unroll
    for (int c = 0; c < 4; c++)
        #pragma unroll
        for (int nt = 0; nt < 4; nt++){
            int col = c*128 + wn*32 + nt*8 + 2*t;
            *(float2*)&p0[col] = make_float2(tf32r(acc[c][nt][0]*inv0),
                                             tf32r(acc[c][nt][1]*inv0));
            *(float2*)&p1[col] = make_float2(tf32r(acc[c][nt][2]*inv1),
                                             tf32r(acc[c][nt][3]*inv1));
        }
}

// ---------------------------------------------------------------------------
// prior + sigma_full
// ---------------------------------------------------------------------------
__global__ void prior_kernel(float* __restrict__ prior, float* __restrict__ sfull)
{
    long row = blockIdx.x;                 // (b*H+h)*T + n
    int n = (int)(row % TT);
    float s = g_sigma[row];
    float inv2 = -1.f / (2.f * s * s);
    float coef = 0.3989422804014327f / s;
    int tid = threadIdx.x;
    int m0 = tid * 4;
    float d0 = (float)(n - (m0 + 0));
    float d1 = (float)(n - (m0 + 1));
    float d2 = (float)(n - (m0 + 2));
    float d3 = (float)(n - (m0 + 3));
    float4 pv;
    pv.x = __expf(d0*d0*inv2) * coef;
    pv.y = __expf(d1*d1*inv2) * coef;
    pv.z = __expf(d2*d2*inv2) * coef;
    pv.w = __expf(d3*d3*inv2) * coef;
    ((float4*)(prior + row * TT))[tid] = pv;
    ((float4*)(sfull + row * TT))[tid] = make_float4(s, s, s, s);
}

// ---------------------------------------------------------------------------
// stylization: g_style[b, 0:1024] = silu(emb[b]) @ emb_W + emb_b
// ---------------------------------------------------------------------------
__global__ void style_kernel(const float* __restrict__ emb,
                             const float* __restrict__ embW,
                             const float* __restrict__ embB)
{
    int bb = blockIdx.y, tid = threadIdx.x;
    __shared__ float se[TEDIM];
    for (int i = tid; i < TEDIM; i += 256) {
        float e = emb[(size_t)bb * TEDIM + i];
        se[i] = siluf(e);
    }
    __syncthreads();
    int j = blockIdx.x * 256 + tid;       // 0..1023
    float acc = 0.f;
    for (int k = 0; k < TEDIM; k++)
        acc += se[k] * embW[(size_t)k * (2*DDIM) + j];
    g_style[bb * (2*DDIM) + j] = acc + embB[j];
}

// ---------------------------------------------------------------------------
// LN2 + scale/shift + silu (hs stored tf32-rounded: feeds out-proj mma)
// ---------------------------------------------------------------------------
__global__ void ln2_style_kernel(const float* __restrict__ g,
                                 const float* __restrict__ b)
{
    int row = blockIdx.x;
    int tid = threadIdx.x;
    int warp = tid >> 5, lane = tid & 31;
    int bb = row / TT;
    const float* yr = g_y + (size_t)row * DDIM;
    float x0 = yr[tid], x1 = yr[tid + 256];
    float s = x0 + x1, sq = x0*x0 + x1*x1;
    #pragma unroll
    for (int o = 16; o > 0; o >>= 1) {
        s  += __shfl_xor_sync(~0u, s,  o);
        sq += __shfl_xor_sync(~0u, sq, o);
    }
    __shared__ float sm[8], sm2[8];
    if (lane == 0) { sm[warp] = s; sm2[warp] = sq; }
    __syncthreads();
    float tot = 0.f, tot2 = 0.f;
    #pragma unroll
    for (int i = 0; i < 8; i++) { tot += sm[i]; tot2 += sm2[i]; }
    float mean = tot * (1.f / DDIM);
    float var  = tot2 * (1.f / DDIM) - mean * mean;
    float rstd = rsqrtf(var + 1e-5f);
    float n0 = (x0 - mean) * rstd * g[tid]       + b[tid];
    float n1 = (x1 - mean) * rstd * g[tid + 256] + b[tid + 256];
    const float* st = g_style + bb * (2*DDIM);
    float h0 = n0 * (1.f + st[tid])       + st[512 + tid];
    float h1 = n1 * (1.f + st[tid + 256]) + st[512 + tid + 256];
    g_hs[(size_t)row*DDIM + tid]       = tf32r(siluf(h0));
    g_hs[(size_t)row*DDIM + tid + 256] = tf32r(siluf(h1));
}

// ---------------------------------------------------------------------------
extern "C" void kernel_launch(void* const* d_in, const int* in_sizes, int n_in,
                              void* d_out, int out_size)
{
    const float* x    = (const float*)d_in[0];
    const float* emb  = (const float*)d_in[1];
    const float* Wq   = (const float*)d_in[2];
    const float* Wk   = (const float*)d_in[3];
    const float* Wv   = (const float*)d_in[4];
    const float* Wsig = (const float*)d_in[5];
    const float* ln1g = (const float*)d_in[6];
    const float* ln1b = (const float*)d_in[7];
    const float* embW = (const float*)d_in[8];
    const float* embB = (const float*)d_in[9];
    const float* ln2g = (const float*)d_in[10];
    const float* ln2b = (const float*)d_in[11];
    const float* outW = (const float*)d_in[12];
    const float* outB = (const float*)d_in[13];

    float* out    = (float*)d_out;
    float* outY   = out;
    float* outS   = out + YN;
    float* outP   = outS + SN;
    float* outSig = outP + SN;

    float *pxn, *pq, *pk, *pv, *py, *phs, *pwr;
    cudaGetSymbolAddress((void**)&pxn, g_xn);
    cudaGetSymbolAddress((void**)&pq,  g_q);
    cudaGetSymbolAddress((void**)&pk,  g_k);
    cudaGetSymbolAddress((void**)&pv,  g_v);
    cudaGetSymbolAddress((void**)&py,  g_y);
    cudaGetSymbolAddress((void**)&phs, g_hs);
    cudaGetSymbolAddress((void**)&pwr, g_wr);

    const int SM128 = 3*(128+128)*20*4;      // 61440
    const int SM64  = 3*(128+64)*20*4;       // 46080
    const int SMF   = 32*68*4 + 2*128*68*4 + 32*4*4;  // 79040

    cudaFuncSetAttribute(tf32_gemm<128,false,true>,  cudaFuncAttributeMaxDynamicSharedMemorySize, SM128);
    cudaFuncSetAttribute(tf32_gemm<128,true ,true>,  cudaFuncAttributeMaxDynamicSharedMemorySize, SM128);
    cudaFuncSetAttribute(tf32_gemm<128,false,false>, cudaFuncAttributeMaxDynamicSharedMemorySize, SM128);
    cudaFuncSetAttribute(tf32_gemm<64 ,false,false>, cudaFuncAttributeMaxDynamicSharedMemorySize, SM64);
    cudaFuncSetAttribute(fused_scores_kernel,        cudaFuncAttributeMaxDynamicSharedMemorySize, SMF);

    // 0) pre-round weights to tf32
    round_w_kernel<<<WSZ/256, 256>>>(Wq, Wk, Wv, outW);

    // 1) LN1 + sigma
    ln1_sigma_kernel<<<MROWS, 256>>>(x, ln1g, ln1b, Wsig);

    // 2) Q/K = xn @ W^T ; V transposed store
    dim3 gq(DDIM/128, MROWS/128, 1);
    tf32_gemm<128,false,true><<<gq, 256, SM128>>>(pxn, pwr,         pq, DDIM, DDIM, DDIM, DDIM,
        1,0,0, 1,0,0, 1,0,0, 1.f, nullptr, nullptr, 0);
    tf32_gemm<128,false,true><<<gq, 256, SM128>>>(pxn, pwr +   WSZ, pk, DDIM, DDIM, DDIM, DDIM,
        1,0,0, 1,0,0, 1,0,0, 1.f, nullptr, nullptr, 0);
    tf32_gemm<128,true ,true><<<gq, 256, SM128>>>(pxn, pwr + 2*WSZ, pv, DDIM, DDIM, DDIM, DDIM,
        1,0,0, 1,0,0, 1,0,0, 1.f, nullptr, nullptr, 0);

    // 3) fused scores + softmax -> series
    fused_scores_kernel<<<dim3(TT/32, BQ*HH), 256, SMF>>>(pq, pk, outS);

    // 4) y = series @ Vt^T  per (b,h)
    dim3 ga(1, TT/128, BQ*HH);
    tf32_gemm<64,false,false><<<ga, 256, SM64>>>(outS, pv, py, TT, TT, DDIM, DDIM,
        1,  (long)TT*TT,    0,
        1,  (long)HD*DDIM,  0,
        HH, (long)TT*DDIM,  (long)HD,
        1.f, nullptr, nullptr, 0);

    // 5) prior + sigma_full
    prior_kernel<<<BQ*HH*TT, 128>>>(outP, outSig);

    // 6) stylization embedding
    style_kernel<<<dim3(4, BQ), 256>>>(emb, embW, embB);

    // 7) LN2 + style + silu
    ln2_style_kernel<<<MROWS, 256>>>(ln2g, ln2b);

    // 8) y_out = x + silu_h @ out_W^T + out_b
    tf32_gemm<128,false,false><<<gq, 256, SM128>>>(phs, pwr + 3*WSZ, outY, DDIM, DDIM, DDIM, DDIM,
        1,0,0, 1,0,0, 1,0,0, 1.f, outB, x, DDIM);
}

// round 5
// speedup vs baseline: 3.0911x; 1.0651x over previous
#include <cuda_runtime.h>

// Problem constants
#define BQ   32
#define TT   512
#define DDIM 512
#define HH   8
#define HD   64
#define TEDIM 2048
#define MROWS (BQ*TT)            // 16384
#define YN ((size_t)BQ*TT*DDIM)  // 8388608
#define SN ((size_t)BQ*HH*TT*TT) // 67108864
#define WSZ (DDIM*DDIM)          // 262144

// Scratch (device globals — no allocation allowed)
__device__ float g_xn[BQ*TT*DDIM];
__device__ float g_q [BQ*TT*DDIM];
__device__ float g_k [BQ*TT*DDIM];
__device__ float g_v [BQ*TT*DDIM];   // stored TRANSPOSED: [b][h*64+d][t]
__device__ float g_y [BQ*TT*DDIM];
__device__ float g_hs[BQ*TT*DDIM];
__device__ float g_sigma[BQ*HH*TT];
__device__ float g_style[BQ*2*DDIM];
__device__ float g_wr[4*WSZ];        // tf32-rounded [Wq;Wk;Wv] (1536x512) + outW

__device__ __forceinline__ float siluf(float z){ return z / (1.f + expf(-z)); }

__device__ __forceinline__ float tf32r(float f){
    unsigned u; asm("cvt.rna.tf32.f32 %0, %1;" : "=r"(u) : "f"(f));
    return __uint_as_float(u);
}

__device__ __forceinline__ void mma8(float* c,
    unsigned a0, unsigned a1, unsigned a2, unsigned a3,
    unsigned b0, unsigned b1)
{
    asm volatile(
        "mma.sync.aligned.m16n8k8.row.col.f32.tf32.tf32.f32 "
        "{%0,%1,%2,%3}, {%4,%5,%6,%7}, {%8,%9}, {%0,%1,%2,%3};"
        : "+f"(c[0]), "+f"(c[1]), "+f"(c[2]), "+f"(c[3])
        : "r"(a0), "r"(a1), "r"(a2), "r"(a3), "r"(b0), "r"(b1));
}

__device__ __forceinline__ void cp16(unsigned dst, const void* src){
    asm volatile("cp.async.cg.shared.global [%0], [%1], 16;" :: "r"(dst), "l"(src));
}
#define CPCOMMIT() asm volatile("cp.async.commit_group;" ::: "memory")
#define CPWAIT(n)  asm volatile("cp.async.wait_group %0;" :: "n"(n) : "memory")

__device__ __forceinline__ uint4 ldmx4(unsigned a){
    uint4 r;
    asm volatile("ldmatrix.sync.aligned.m8n8.x4.shared.b16 {%0,%1,%2,%3}, [%4];"
        : "=r"(r.x), "=r"(r.y), "=r"(r.z), "=r"(r.w) : "r"(a));
    return r;
}

// ---------------------------------------------------------------------------
// weight pre-round
// ---------------------------------------------------------------------------
__global__ void round_w_kernel(const float* __restrict__ w0, const float* __restrict__ w1,
                               const float* __restrict__ w2, const float* __restrict__ w3)
{
    int i = blockIdx.x * 256 + threadIdx.x;
    g_wr[i]         = tf32r(w0[i]);
    g_wr[i +   WSZ] = tf32r(w1[i]);
    g_wr[i + 2*WSZ] = tf32r(w2[i]);
    g_wr[i + 3*WSZ] = tf32r(w3[i]);
}

// ---------------------------------------------------------------------------
// LN1 + sigma (xn stored tf32-rounded)
// ---------------------------------------------------------------------------
__global__ void ln1_sigma_kernel(const float* __restrict__ x,
                                 const float* __restrict__ g,
                                 const float* __restrict__ b,
                                 const float* __restrict__ Wsig)
{
    int row = blockIdx.x;
    int tid = threadIdx.x;
    int warp = tid >> 5, lane = tid & 31;
    const float* xr = x + (size_t)row * DDIM;
    float x0 = xr[tid], x1 = xr[tid + 256];
    float s = x0 + x1, sq = x0*x0 + x1*x1;
    #pragma unroll
    for (int o = 16; o > 0; o >>= 1) {
        s  += __shfl_xor_sync(~0u, s,  o);
        sq += __shfl_xor_sync(~0u, sq, o);
    }
    __shared__ float sm[8], sm2[8];
    if (lane == 0) { sm[warp] = s; sm2[warp] = sq; }
    __syncthreads();
    float tot = 0.f, tot2 = 0.f;
    #pragma unroll
    for (int i = 0; i < 8; i++) { tot += sm[i]; tot2 += sm2[i]; }
    float mean = tot * (1.f / DDIM);
    float var  = tot2 * (1.f / DDIM) - mean * mean;
    float rstd = rsqrtf(var + 1e-5f);
    g_xn[(size_t)row*DDIM + tid]       = tf32r((x0 - mean) * rstd * g[tid]       + b[tid]);
    g_xn[(size_t)row*DDIM + tid + 256] = tf32r((x1 - mean) * rstd * g[tid + 256] + b[tid + 256]);

    float acc[HH];
    #pragma unroll
    for (int h = 0; h < HH; h++)
        acc[h] = x0 * Wsig[tid*HH + h] + x1 * Wsig[(tid+256)*HH + h];
    #pragma unroll
    for (int h = 0; h < HH; h++)
        #pragma unroll
        for (int o = 16; o > 0; o >>= 1)
            acc[h] += __shfl_xor_sync(~0u, acc[h], o);
    __shared__ float red[8][HH];
    if (lane == 0)
        #pragma unroll
        for (int h = 0; h < HH; h++) red[warp][h] = acc[h];
    __syncthreads();
    if (tid < HH) {
        float z = 0.f;
        #pragma unroll
        for (int w = 0; w < 8; w++) z += red[w][tid];
        float sg  = 1.f / (1.f + expf(-5.f * z)) + 1e-5f;
        float sig = exp2f(sg * 1.5849625007211562f) - 1.f;   // 3^sg - 1
        int bb = row / TT, t = row % TT;
        g_sigma[(bb*HH + tid)*TT + t] = sig;
    }
}

// ---------------------------------------------------------------------------
// tf32 NT GEMM v2 (BK=32, 3-stage cp.async, merged-QKV routing / outproj).
// ---------------------------------------------------------------------------
template<bool QKV>
__global__ void __launch_bounds__(256,2)
tf32_gemm2(const float* __restrict__ A, const float* __restrict__ Bw,
           float* __restrict__ Cq, float* __restrict__ Ck, float* __restrict__ Cv,
           const float* __restrict__ bias, const float* __restrict__ res)
{
    constexpr int ST  = 36;                // 32 + 4 pad (floats)
    constexpr int STG = 128*ST*4;          // per-operand stage bytes

    extern __shared__ float dsm[];
    const unsigned sb = (unsigned)__cvta_generic_to_shared(dsm);
    const unsigned aS = sb;
    const unsigned bS = sb + 3*STG;

    const int tid  = threadIdx.x;
    const int lane = tid & 31;
    const int wid  = tid >> 5;
    const int wm   = wid & 1;
    const int wn   = wid >> 1;
    const int g    = lane >> 2;
    const int t    = lane & 3;

    const int m0 = blockIdx.y * 128;
    const int n0 = blockIdx.x * 128;

    const int rl = tid >> 3;               // 0..31
    const int qc = tid & 7;                // 16B chunk in BK32

    const float* Ag = A  + (long)(m0 + rl) * 512 + qc*4;
    const float* Bg = Bw + (long)(n0 + rl) * 512 + qc*4;
    const unsigned dA = (unsigned)(rl*ST + qc*4) * 4;

    auto issue = [&](int st, int k0){
        unsigned ab = aS + st*STG, bb = bS + st*STG;
        #pragma unroll
        for (int e = 0; e < 4; e++){
            cp16(ab + dA + e*32*ST*4, Ag + (long)e*32*512 + k0);
            cp16(bb + dA + e*32*ST*4, Bg + (long)e*32*512 + k0);
        }
    };

    const int arow = (lane & 7) + ((lane >> 3) & 1) * 8;
    const int acol = (lane >> 4) * 4;
    const unsigned aFB = (unsigned)((wm*64 + arow)*ST + acol) * 4;
    const unsigned bFB = (unsigned)((wn*32 + (lane & 7))*ST + (lane >> 3)*4) * 4;

    float acc[4][4][4];
    #pragma unroll
    for (int i = 0; i < 4; i++)
        #pragma unroll
        for (int j = 0; j < 4; j++)
            #pragma unroll
            for (int p = 0; p < 4; p++) acc[i][j][p] = 0.f;

    issue(0, 0);  CPCOMMIT();
    issue(1, 32); CPCOMMIT();

    int buf = 0;
    for (int k0 = 0; k0 < 512; k0 += 32) {
        CPWAIT(1);
        __syncthreads();
        if (k0 + 64 < 512) {
            int nb = buf + 2; if (nb >= 3) nb -= 3;
            issue(nb, k0 + 64);
        }
        CPCOMMIT();

        const unsigned ab = aS + buf*STG;
        const unsigned bb = bS + buf*STG;

        uint4 bfr[4][2];
        #pragma unroll
        for (int nt = 0; nt < 4; nt++)
            #pragma unroll
            for (int kg = 0; kg < 2; kg++)
                bfr[nt][kg] = ldmx4(bb + bFB + (unsigned)(nt*8*ST + kg*16)*4);

        #pragma unroll
        for (int ks = 0; ks < 4; ks++) {
            #pragma unroll
            for (int mt = 0; mt < 4; mt++) {
                uint4 a = ldmx4(ab + aFB + (unsigned)(mt*16*ST + ks*8)*4);
                #pragma unroll
                for (int nt = 0; nt < 4; nt++)
                    mma8(acc[mt][nt], a.x, a.y, a.z, a.w,
                         (ks & 1) ? bfr[nt][ks>>1].z : bfr[nt][ks>>1].x,
                         (ks & 1) ? bfr[nt][ks>>1].w : bfr[nt][ks>>1].y);
            }
        }
        buf++; if (buf == 3) buf = 0;
    }

    // Epilogue
    #pragma unroll
    for (int mt = 0; mt < 4; mt++){
        #pragma unroll
        for (int nt = 0; nt < 4; nt++){
            int row = m0 + wm*64 + mt*16 + g;
            int col = n0 + wn*32 + nt*8 + 2*t;
            float v0 = acc[mt][nt][0], v1 = acc[mt][nt][1];
            float v2 = acc[mt][nt][2], v3 = acc[mt][nt][3];
            if (QKV){
                v0 = tf32r(v0); v1 = tf32r(v1); v2 = tf32r(v2); v3 = tf32r(v3);
                if (n0 < 512){
                    *(float2*)&Cq[(long)row*512 + col]     = make_float2(v0, v1);
                    *(float2*)&Cq[(long)(row+8)*512 + col] = make_float2(v2, v3);
                } else if (n0 < 1024){
                    int c2 = col - 512;
                    *(float2*)&Ck[(long)row*512 + c2]     = make_float2(v0, v1);
                    *(float2*)&Ck[(long)(row+8)*512 + c2] = make_float2(v2, v3);
                } else {
                    int vc = col - 1024;
                    long base0 = (long)(row >> 9) * (512L*512) + (row & 511);
                    Cv[base0 + (long)vc*512]         = v0;
                    Cv[base0 + (long)(vc+1)*512]     = v1;
                    Cv[base0 + 8 + (long)vc*512]     = v2;
                    Cv[base0 + 8 + (long)(vc+1)*512] = v3;
                }
            } else {
                v0 += bias[col];   v1 += bias[col+1];
                v2 += bias[col];   v3 += bias[col+1];
                v0 += res[(long)row*512 + col];
                v1 += res[(long)row*512 + col+1];
                v2 += res[(long)(row+8)*512 + col];
                v3 += res[(long)(row+8)*512 + col+1];
                *(float2*)&Cq[(long)row*512 + col]     = make_float2(v0, v1);
                *(float2*)&Cq[(long)(row+8)*512 + col] = make_float2(v2, v3);
            }
        }
    }
}

// ---------------------------------------------------------------------------
// ROUND-3 (proven) tf32 NT GEMM: BK=16, 3-stage cp.async. Used for AV only.
// ---------------------------------------------------------------------------
template<int BN, bool TRANSC, bool ROUND>
__global__ void __launch_bounds__(256,2)
tf32_gemm(const float* __restrict__ A, const float* __restrict__ Bm,
          float* __restrict__ C, int K, int lda, int ldb, int ldc,
          int divA, long sA1, long sA2,
          int divB, long sB1, long sB2,
          int divC, long sC1, long sC2,
          float scale, const float* __restrict__ bias,
          const float* __restrict__ res, int ldres)
{
    constexpr int ST   = 20;
    constexpr int ASTB = 128*ST*4;
    constexpr int BSTB = BN*ST*4;
    constexpr int WT_N = BN / 4;
    constexpr int NT   = WT_N / 8;

    extern __shared__ float dsm[];
    const unsigned sb = (unsigned)__cvta_generic_to_shared(dsm);
    const unsigned aS = sb;
    const unsigned bS = sb + 3*ASTB;

    const int tid  = threadIdx.x;
    const int lane = tid & 31;
    const int wid  = tid >> 5;
    const int wm   = wid & 1;
    const int wn   = wid >> 1;
    const int g    = lane >> 2;
    const int t    = lane & 3;

    const int z = blockIdx.z;
    A  += (long)(z / divA) * sA1 + (long)(z % divA) * sA2;
    Bm += (long)(z / divB) * sB1 + (long)(z % divB) * sB2;
    if (!TRANSC)
        C += (long)(z / divC) * sC1 + (long)(z % divC) * sC2;

    const int m0 = blockIdx.y * 128;
    const int n0 = blockIdx.x * BN;

    const int rl = tid >> 2;
    const int q  = tid & 3;

    const float* Ag0 = A  + (long)(m0 + rl) * lda + q*4;
    const float* Ag1 = Ag0 + 64L * lda;
    const float* Bg0 = Bm + (long)(n0 + rl) * ldb + q*4;
    const float* Bg1 = Bg0 + 64L * ldb;

    const unsigned d0 = (unsigned)(rl*ST + q*4) * 4;
    const unsigned d1 = (unsigned)((rl+64)*ST + q*4) * 4;

    const int arow = (lane & 7) + ((lane >> 3) & 1) * 8;
    const int acol = (lane >> 4) * 4;
    const unsigned aFB = (unsigned)((wm*64 + arow)*ST + acol) * 4;
    const unsigned bFB = (unsigned)((wn*WT_N + (lane & 7))*ST + (lane >> 3)*4) * 4;

    float acc[4][NT][4];
    #pragma unroll
    for (int i = 0; i < 4; i++)
        #pragma unroll
        for (int j = 0; j < NT; j++)
            #pragma unroll
            for (int p = 0; p < 4; p++) acc[i][j][p] = 0.f;

    auto issue = [&](int st, int k0){
        unsigned ab = aS + st*ASTB, bb = bS + st*BSTB;
        cp16(ab + d0, Ag0 + k0);
        cp16(ab + d1, Ag1 + k0);
        cp16(bb + d0, Bg0 + k0);
        if (BN == 128) cp16(bb + d1, Bg1 + k0);
    };

    issue(0, 0);  CPCOMMIT();
    issue(1, 16); CPCOMMIT();

    int buf = 0;
    for (int k0 = 0; k0 < K; k0 += 16) {
        CPWAIT(1);
        __syncthreads();
        if (k0 + 32 < K) {
            int nb = buf + 2; if (nb >= 3) nb -= 3;
            issue(nb, k0 + 32);
        }
        CPCOMMIT();

        const unsigned ab = aS + buf*ASTB;
        const unsigned bb = bS + buf*BSTB;

        uint4 bfr[NT];
        #pragma unroll
        for (int nt = 0; nt < NT; nt++)
            bfr[nt] = ldmx4(bb + bFB + (unsigned)(nt*8*ST*4));

        #pragma unroll
        for (int ks = 0; ks < 2; ks++) {
            #pragma unroll
            for (int mt = 0; mt < 4; mt++) {
                uint4 a = ldmx4(ab + aFB + (unsigned)(mt*16*ST*4 + ks*32));
                #pragma unroll
                for (int nt = 0; nt < NT; nt++)
                    mma8(acc[mt][nt], a.x, a.y, a.z, a.w,
                         ks ? bfr[nt].z : bfr[nt].x,
                         ks ? bfr[nt].w : bfr[nt].y);
            }
        }
        buf++; if (buf == 3) buf = 0;
    }

    #pragma unroll
    for (int mt = 0; mt < 4; mt++){
        #pragma unroll
        for (int nt = 0; nt < NT; nt++){
            int row = m0 + wm*64 + mt*16 + g;
            int col = n0 + wn*WT_N + nt*8 + 2*t;
            float v0 = acc[mt][nt][0]*scale, v1 = acc[mt][nt][1]*scale;
            float v2 = acc[mt][nt][2]*scale, v3 = acc[mt][nt][3]*scale;
            if (bias){
                v0 += bias[col]; v1 += bias[col+1];
                v2 += bias[col]; v3 += bias[col+1];
            }
            if (res){
                v0 += res[(long)row*ldres + col];
                v1 += res[(long)row*ldres + col+1];
                v2 += res[(long)(row+8)*ldres + col];
                v3 += res[(long)(row+8)*ldres + col+1];
            }
            if (ROUND){
                v0 = tf32r(v0); v1 = tf32r(v1); v2 = tf32r(v2); v3 = tf32r(v3);
            }
            if (TRANSC){
                long base0 = (long)(row >> 9) * (512L*512) + (row & 511);
                C[base0 + (long)col*512]         = v0;
                C[base0 + (long)(col+1)*512]     = v1;
                C[base0 + 8 + (long)col*512]     = v2;
                C[base0 + 8 + (long)(col+1)*512] = v3;
            } else {
                *(float2*)&C[(long)row*ldc + col]     = make_float2(v0, v1);
                *(float2*)&C[(long)(row+8)*ldc + col] = make_float2(v2, v3);
            }
        }
    }
}

// ---------------------------------------------------------------------------
// Fused scores + softmax (ROUND-3 proven version): series written tf32-rounded.
// ---------------------------------------------------------------------------
__global__ void __launch_bounds__(256,2)
fused_scores_kernel(const float* __restrict__ Q, const float* __restrict__ Kt,
                    float* __restrict__ S)
{
    constexpr int AST = 68;
    constexpr int BST = 68;
    const unsigned A_BYTES = 32*AST*4;            // 8704
    const unsigned B_BYTES = 128*BST*4;           // 34816

    extern __shared__ float dsm[];
    const unsigned sb  = (unsigned)__cvta_generic_to_shared(dsm);
    const unsigned sbA = sb;
    const unsigned sbB = sb + A_BYTES;
    float* red = dsm + (A_BYTES + 2*B_BYTES)/4;   // [32][4]

    const int tid  = threadIdx.x;
    const int lane = tid & 31;
    const int wid  = tid >> 5;
    const int wm   = wid & 1;
    const int wn   = wid >> 1;
    const int g    = lane >> 2;
    const int t    = lane & 3;

    const int bh = blockIdx.y;
    const int b  = bh >> 3, h = bh & 7;
    const int m0 = blockIdx.x * 32;

    const float* Qb = Q + ((long)b*512 + m0)*512 + h*64;
    const float* Kb = Kt + ((long)b*512)*512 + h*64;
    float* Sb = S + ((long)bh*512 + m0)*512;

    const int arow = (lane & 7) + ((lane >> 3) & 1) * 8;
    const int acol = (lane >> 4) * 4;
    const unsigned aF = sbA + (unsigned)((wm*16 + arow)*AST + acol) * 4;
    const unsigned bF = (unsigned)((wn*32 + (lane & 7))*BST + (lane >> 3)*4) * 4;

    auto issueB = [&](int chunk, int bufb){
        unsigned dst = sbB + (unsigned)bufb * B_BYTES;
        const float* src = Kb + (long)(chunk*128)*512;
        #pragma unroll
        for (int e = 0; e < 8; e++){
            int idx = tid + 256*e;
            int r = idx >> 4, c4 = idx & 15;
            cp16(dst + (unsigned)(r*BST + c4*4)*4, src + (long)r*512 + c4*4);
        }
    };

    {
        #pragma unroll
        for (int e = 0; e < 2; e++){
            int idx = tid + 256*e;
            int r = idx >> 4, c4 = idx & 15;
            cp16(sbA + (unsigned)(r*AST + c4*4)*4, Qb + (long)r*512 + c4*4);
        }
        issueB(0, 0);
        CPCOMMIT();
    }

    float acc[4][4][4];
    #pragma unroll
    for (int c = 0; c < 4; c++)
        #pragma unroll
        for (int nt = 0; nt < 4; nt++)
            #pragma unroll
            for (int p = 0; p < 4; p++) acc[c][nt][p] = 0.f;

    for (int c = 0; c < 4; c++){
        CPWAIT(0);
        __syncthreads();
        if (c + 1 < 4) issueB(c + 1, (c + 1) & 1);
        CPCOMMIT();

        const unsigned bb = sbB + (unsigned)(c & 1) * B_BYTES;
        #pragma unroll
        for (int kg = 0; kg < 4; kg++){
            uint4 a0 = ldmx4(aF + (unsigned)(kg*16 + 0)*4);
            uint4 a1 = ldmx4(aF + (unsigned)(kg*16 + 8)*4);
            #pragma unroll
            for (int nt = 0; nt < 4; nt++){
                uint4 bv = ldmx4(bb + bF + (unsigned)(nt*8*BST + kg*16)*4);
                mma8(acc[c][nt], a0.x, a0.y, a0.z, a0.w, bv.x, bv.y);
                mma8(acc[c][nt], a1.x, a1.y, a1.z, a1.w, bv.z, bv.w);
            }
        }
        __syncthreads();
    }

    #pragma unroll
    for (int c = 0; c < 4; c++)
        #pragma unroll
        for (int nt = 0; nt < 4; nt++)
            #pragma unroll
            for (int p = 0; p < 4; p++) acc[c][nt][p] *= (1.f/64.f);

    const int r0 = wm*16 + g, r1 = r0 + 8;

    float mx0 = -1e30f, mx1 = -1e30f;
    #pragma unroll
    for (int c = 0; c < 4; c++)
        #pragma unroll
        for (int nt = 0; nt < 4; nt++){
            mx0 = fmaxf(mx0, fmaxf(acc[c][nt][0], acc[c][nt][1]));
            mx1 = fmaxf(mx1, fmaxf(acc[c][nt][2], acc[c][nt][3]));
        }
    #pragma unroll
    for (int o = 1; o <= 2; o <<= 1){
        mx0 = fmaxf(mx0, __shfl_xor_sync(~0u, mx0, o));
        mx1 = fmaxf(mx1, __shfl_xor_sync(~0u, mx1, o));
    }
    if (t == 0){ red[r0*4 + wn] = mx0; red[r1*4 + wn] = mx1; }
    __syncthreads();
    float rm0 = fmaxf(fmaxf(red[r0*4+0], red[r0*4+1]), fmaxf(red[r0*4+2], red[r0*4+3]));
    float rm1 = fmaxf(fmaxf(red[r1*4+0], red[r1*4+1]), fmaxf(red[r1*4+2], red[r1*4+3]));
    __syncthreads();

    float s0 = 0.f, s1 = 0.f;
    #pragma unroll
    for (int c = 0; c < 4; c++)
        #pragma unroll
        for (int nt = 0; nt < 4; nt++){
            acc[c][nt][0] = __expf(acc[c][nt][0] - rm0);
            acc[c][nt][1] = __expf(acc[c][nt][1] - rm0);
            acc[c][nt][2] = __expf(acc[c][nt][2] - rm1);
            acc[c][nt][3] = __expf(acc[c][nt][3] - rm1);
            s0 += acc[c][nt][0] + acc[c][nt][1];
            s1 += acc[c][nt][2] + acc[c][nt][3];
        }
    #pragma unroll
    for (int o = 1; o <= 2; o <<= 1){
        s0 += __shfl_xor_sync(~0u, s0, o);
        s1 += __shfl_xor_sync(~0u, s1, o);
    }
    if (t == 0){ red[r0*4 + wn] = s0; red[r1*4 + wn] = s1; }
    __syncthreads();
    float inv0 = 1.f / (red[r0*4+0] + red[r0*4+1] + red[r0*4+2] + red[r0*4+3]);
    float inv1 = 1.f / (red[r1*4+0] + red[r1*4+1] + red[r1*4+2] + red[r1*4+3]);

    float* p0 = Sb + (long)r0*512;
    float* p1 = Sb + (long)r1*512;
    #pragma unroll
    for (int c = 0; c < 4; c++)
        #pragma unroll
        for (int nt = 0; nt < 4; nt++){
            int col = c*128 + wn*32 + nt*8 + 2*t;
            *(float2*)&p0[col] = make_float2(tf32r(acc[c][nt][0]*inv0),
                                             tf32r(acc[c][nt][1]*inv0));
            *(float2*)&p1[col] = make_float2(tf32r(acc[c][nt][2]*inv1),
                                             tf32r(acc[c][nt][3]*inv1));
        }
}

// ---------------------------------------------------------------------------
// prior + sigma_full
// ---------------------------------------------------------------------------
__global__ void prior_kernel(float* __restrict__ prior, float* __restrict__ sfull)
{
    long row = blockIdx.x;
    int n = (int)(row % TT);
    float s = g_sigma[row];
    float inv2 = -1.f / (2.f * s * s);
    float coef = 0.3989422804014327f / s;
    int tid = threadIdx.x;
    int m0 = tid * 4;
    float d0 = (float)(n - (m0 + 0));
    float d1 = (float)(n - (m0 + 1));
    float d2 = (float)(n - (m0 + 2));
    float d3 = (float)(n - (m0 + 3));
    float4 pv;
    pv.x = __expf(d0*d0*inv2) * coef;
    pv.y = __expf(d1*d1*inv2) * coef;
    pv.z = __expf(d2*d2*inv2) * coef;
    pv.w = __expf(d3*d3*inv2) * coef;
    ((float4*)(prior + row * TT))[tid] = pv;
    ((float4*)(sfull + row * TT))[tid] = make_float4(s, s, s, s);
}

// ---------------------------------------------------------------------------
// stylization
// ---------------------------------------------------------------------------
__global__ void style_kernel(const float* __restrict__ emb,
                             const float* __restrict__ embW,
                             const float* __restrict__ embB)
{
    int bb = blockIdx.y, tid = threadIdx.x;
    __shared__ float se[TEDIM];
    for (int i = tid; i < TEDIM; i += 256) {
        float e = emb[(size_t)bb * TEDIM + i];
        se[i] = siluf(e);
    }
    __syncthreads();
    int j = blockIdx.x * 256 + tid;
    float acc = 0.f;
    for (int k = 0; k < TEDIM; k++)
        acc += se[k] * embW[(size_t)k * (2*DDIM) + j];
    g_style[bb * (2*DDIM) + j] = acc + embB[j];
}

// ---------------------------------------------------------------------------
// LN2 + scale/shift + silu (hs stored tf32-rounded)
// ---------------------------------------------------------------------------
__global__ void ln2_style_kernel(const float* __restrict__ g,
                                 const float* __restrict__ b)
{
    int row = blockIdx.x;
    int tid = threadIdx.x;
    int warp = tid >> 5, lane = tid & 31;
    int bb = row / TT;
    const float* yr = g_y + (size_t)row * DDIM;
    float x0 = yr[tid], x1 = yr[tid + 256];
    float s = x0 + x1, sq = x0*x0 + x1*x1;
    #pragma unroll
    for (int o = 16; o > 0; o >>= 1) {
        s  += __shfl_xor_sync(~0u, s,  o);
        sq += __shfl_xor_sync(~0u, sq, o);
    }
    __shared__ float sm[8], sm2[8];
    if (lane == 0) { sm[warp] = s; sm2[warp] = sq; }
    __syncthreads();
    float tot = 0.f, tot2 = 0.f;
    #pragma unroll
    for (int i = 0; i < 8; i++) { tot += sm[i]; tot2 += sm2[i]; }
    float mean = tot * (1.f / DDIM);
    float var  = tot2 * (1.f / DDIM) - mean * mean;
    float rstd = rsqrtf(var + 1e-5f);
    float n0 = (x0 - mean) * rstd * g[tid]       + b[tid];
    float n1 = (x1 - mean) * rstd * g[tid + 256] + b[tid + 256];
    const float* st = g_style + bb * (2*DDIM);
    float h0 = n0 * (1.f + st[tid])       + st[512 + tid];
    float h1 = n1 * (1.f + st[tid + 256]) + st[512 + tid + 256];
    g_hs[(size_t)row*DDIM + tid]       = tf32r(siluf(h0));
    g_hs[(size_t)row*DDIM + tid + 256] = tf32r(siluf(h1));
}

// ---------------------------------------------------------------------------
extern "C" void kernel_launch(void* const* d_in, const int* in_sizes, int n_in,
                              void* d_out, int out_size)
{
    const float* x    = (const float*)d_in[0];
    const float* emb  = (const float*)d_in[1];
    const float* Wq   = (const float*)d_in[2];
    const float* Wk   = (const float*)d_in[3];
    const float* Wv   = (const float*)d_in[4];
    const float* Wsig = (const float*)d_in[5];
    const float* ln1g = (const float*)d_in[6];
    const float* ln1b = (const float*)d_in[7];
    const float* embW = (const float*)d_in[8];
    const float* embB = (const float*)d_in[9];
    const float* ln2g = (const float*)d_in[10];
    const float* ln2b = (const float*)d_in[11];
    const float* outW = (const float*)d_in[12];
    const float* outB = (const float*)d_in[13];

    float* out    = (float*)d_out;
    float* outY   = out;
    float* outS   = out + YN;
    float* outP   = outS + SN;
    float* outSig = outP + SN;

    float *pxn, *pq, *pk, *pv, *py, *phs, *pwr;
    cudaGetSymbolAddress((void**)&pxn, g_xn);
    cudaGetSymbolAddress((void**)&pq,  g_q);
    cudaGetSymbolAddress((void**)&pk,  g_k);
    cudaGetSymbolAddress((void**)&pv,  g_v);
    cudaGetSymbolAddress((void**)&py,  g_y);
    cudaGetSymbolAddress((void**)&phs, g_hs);
    cudaGetSymbolAddress((void**)&pwr, g_wr);

    const int SMG = 3*2*128*36*4;                 // 110592
    const int SM64 = 3*(128+64)*20*4;             // 46080
    const int SMF  = 32*68*4 + 2*128*68*4 + 32*4*4; // 78848

    cudaFuncSetAttribute(tf32_gemm2<true >, cudaFuncAttributeMaxDynamicSharedMemorySize, SMG);
    cudaFuncSetAttribute(tf32_gemm2<false>, cudaFuncAttributeMaxDynamicSharedMemorySize, SMG);
    cudaFuncSetAttribute(tf32_gemm<64,false,false>, cudaFuncAttributeMaxDynamicSharedMemorySize, SM64);
    cudaFuncSetAttribute(fused_scores_kernel, cudaFuncAttributeMaxDynamicSharedMemorySize, SMF);

    // 0) pre-round weights to tf32 (g_wr[0:3*WSZ] = merged [1536,512] QKV)
    round_w_kernel<<<WSZ/256, 256>>>(Wq, Wk, Wv, outW);

    // 1) LN1 + sigma
    ln1_sigma_kernel<<<MROWS, 256>>>(x, ln1g, ln1b, Wsig);

    // 2) merged QKV projection (one launch, per-block routing)
    tf32_gemm2<true><<<dim3(12, MROWS/128), 256, SMG>>>(
        pxn, pwr, pq, pk, pv, nullptr, nullptr);

    // 3) fused scores + softmax -> series (tf32-rounded, proven path)
    fused_scores_kernel<<<dim3(TT/32, BQ*HH), 256, SMF>>>(pq, pk, outS);

    // 4) y = series @ Vt^T per (b,h) (round-3 proven BK=16 core)
    dim3 ga(1, TT/128, BQ*HH);
    tf32_gemm<64,false,false><<<ga, 256, SM64>>>(outS, pv, py, TT, TT, DDIM, DDIM,
        1,  (long)TT*TT,    0,
        1,  (long)HD*DDIM,  0,
        HH, (long)TT*DDIM,  (long)HD,
        1.f, nullptr, nullptr, 0);

    // 5) prior + sigma_full
    prior_kernel<<<BQ*HH*TT, 128>>>(outP, outSig);

    // 6) stylization embedding
    style_kernel<<<dim3(4, BQ), 256>>>(emb, embW, embB);

    // 7) LN2 + style + silu
    ln2_style_kernel<<<MROWS, 256>>>(ln2g, ln2b);

    // 8) y_out = x + silu_h @ out_W^T + out_b
    tf32_gemm2<false><<<dim3(4, MROWS/128), 256, SMG>>>(
        phs, pwr + 3*WSZ, outY, nullptr, nullptr, outB, x);
}